// round 1
// baseline (speedup 1.0000x reference)
#include <cuda_runtime.h>
#include <cuda_bf16.h>
#include <cstddef>

#define NN 50000
#define NE 600000
#define D 128
#define BN_EPS 1e-5f

// ---------------- scratch (device globals; no runtime allocation) -------------
__device__ float g_h[NN * D];        // node features between layers
__device__ float g_agg[NN * D];      // scatter-add destination
__device__ float g_mid[NN * 2 * D];  // hidden after Linear1+ReLU
__device__ float g_h2[NN * D];       // after Linear2 (pre-BN)
__device__ float g_sum[D];
__device__ float g_sumsq[D];

// ---------------- input embedding: h = atom[x0] + chir[x1] + hyb[x2] ----------
__global__ void embed_kernel(const int* __restrict__ x,
                             const float* __restrict__ atom,
                             const float* __restrict__ chir,
                             const float* __restrict__ hyb) {
    int t = blockIdx.x * blockDim.x + threadIdx.x;
    int node = t >> 5, lane = t & 31;
    if (node >= NN) return;
    int x0 = x[node * 3 + 0];
    int x1 = x[node * 3 + 1];
    int x2 = x[node * 3 + 2];
    float4 a = ((const float4*)(atom + (size_t)x0 * D))[lane];
    float4 c = ((const float4*)(chir + (size_t)x1 * D))[lane];
    float4 y = ((const float4*)(hyb  + (size_t)x2 * D))[lane];
    float4 r = make_float4(a.x + c.x + y.x, a.y + c.y + y.y,
                           a.z + c.z + y.z, a.w + c.w + y.w);
    ((float4*)g_h)[(size_t)node * 32 + lane] = r;
}

// ---------------- edge message + scatter-add (one warp per edge) --------------
__global__ void scatter_kernel(const int* __restrict__ ei,
                               const int* __restrict__ ea,
                               const float* __restrict__ e1l,
                               const float* __restrict__ e2l) {
    int t = blockIdx.x * blockDim.x + threadIdx.x;
    int e = t >> 5, lane = t & 31;
    if (e >= NE) return;
    int s  = ei[e];
    int dn = ei[NE + e];
    int a0 = ea[2 * e + 0];
    int a1 = ea[2 * e + 1];
    float4 vh = ((const float4*)g_h)[(size_t)s * 32 + lane];
    float4 v1 = ((const float4*)(e1l + (size_t)a0 * D))[lane];
    float4 v2 = ((const float4*)(e2l + (size_t)a1 * D))[lane];
    float* dst = g_agg + (size_t)dn * D + lane * 4;
    atomicAdd(dst + 0, vh.x + v1.x + v2.x);
    atomicAdd(dst + 1, vh.y + v1.y + v2.y);
    atomicAdd(dst + 2, vh.z + v1.z + v2.z);
    atomicAdd(dst + 3, vh.w + v1.w + v2.w);
}

// ---------------- fp32 tiled GEMM: C = act(A@B + bias) ------------------------
// BM=BN=128, BK=16, 256 threads, 8x8 register tile per thread.
__global__ __launch_bounds__(256) void gemm_kernel(
    const float* __restrict__ A, const float* __restrict__ B,
    const float* __restrict__ bias, float* __restrict__ C,
    int M, int N, int K, int relu) {
    __shared__ __align__(16) float As[16][128];
    __shared__ __align__(16) float Bs[16][128];
    const int tid = threadIdx.x;
    const int cCol = blockIdx.x, cRow = blockIdx.y;
    const int threadCol = tid & 15;          // 0..15
    const int threadRow = tid >> 4;          // 0..15
    const int innerRowA = tid >> 2;          // 0..63
    const int innerColA = (tid & 3) << 2;    // 0,4,8,12
    const int innerRowB = tid >> 5;          // 0..7
    const int innerColB = (tid & 31) << 2;   // 0..124

    const float* Ab = A + (size_t)cRow * 128 * K;
    const float* Bb = B + cCol * 128;
    float acc[8][8];
#pragma unroll
    for (int i = 0; i < 8; i++)
#pragma unroll
        for (int j = 0; j < 8; j++) acc[i][j] = 0.f;

    for (int k0 = 0; k0 < K; k0 += 16) {
#pragma unroll
        for (int p = 0; p < 128; p += 64) {
            int r = innerRowA + p;
            int gm = cRow * 128 + r;
            float4 v = make_float4(0.f, 0.f, 0.f, 0.f);
            if (gm < M) v = *(const float4*)(Ab + (size_t)r * K + k0 + innerColA);
            As[innerColA + 0][r] = v.x;
            As[innerColA + 1][r] = v.y;
            As[innerColA + 2][r] = v.z;
            As[innerColA + 3][r] = v.w;
        }
#pragma unroll
        for (int p = 0; p < 16; p += 8) {
            int r = innerRowB + p;
            *(float4*)&Bs[r][innerColB] =
                *(const float4*)(Bb + (size_t)(k0 + r) * N + innerColB);
        }
        __syncthreads();
#pragma unroll
        for (int k = 0; k < 16; k++) {
            float4 a0 = *(const float4*)&As[k][threadRow * 8];
            float4 a1 = *(const float4*)&As[k][threadRow * 8 + 4];
            float4 b0 = *(const float4*)&Bs[k][threadCol * 8];
            float4 b1 = *(const float4*)&Bs[k][threadCol * 8 + 4];
            float ra[8] = {a0.x, a0.y, a0.z, a0.w, a1.x, a1.y, a1.z, a1.w};
            float rb[8] = {b0.x, b0.y, b0.z, b0.w, b1.x, b1.y, b1.z, b1.w};
#pragma unroll
            for (int i = 0; i < 8; i++)
#pragma unroll
                for (int j = 0; j < 8; j++) acc[i][j] += ra[i] * rb[j];
        }
        __syncthreads();
    }
    // epilogue: bias + optional ReLU
    int n0 = cCol * 128 + threadCol * 8;
    float bv[8];
#pragma unroll
    for (int j = 0; j < 8; j++) bv[j] = bias[n0 + j];
#pragma unroll
    for (int i = 0; i < 8; i++) {
        int gm = cRow * 128 + threadRow * 8 + i;
        if (gm < M) {
            float vals[8];
#pragma unroll
            for (int j = 0; j < 8; j++) {
                float v = acc[i][j] + bv[j];
                if (relu) v = fmaxf(v, 0.f);
                vals[j] = v;
            }
            *(float4*)(C + (size_t)gm * N + n0) =
                make_float4(vals[0], vals[1], vals[2], vals[3]);
            *(float4*)(C + (size_t)gm * N + n0 + 4) =
                make_float4(vals[4], vals[5], vals[6], vals[7]);
        }
    }
}

// ---------------- BN batch statistics ------------------------------------------
__global__ void zero_stats_kernel() {
    g_sum[threadIdx.x] = 0.f;
    g_sumsq[threadIdx.x] = 0.f;
}

__global__ void stats_kernel(const float* __restrict__ h2) {
    int col = threadIdx.x & 127;
    int rpb = blockDim.x >> 7;                  // rows handled per block per step
    int r = blockIdx.x * rpb + (threadIdx.x >> 7);
    int stride = gridDim.x * rpb;
    float s = 0.f, s2 = 0.f;
    for (; r < NN; r += stride) {
        float v = h2[(size_t)r * D + col];
        s += v;
        s2 += v * v;
    }
    atomicAdd(&g_sum[col], s);
    atomicAdd(&g_sumsq[col], s2);
}

__global__ void bn_kernel(const float* __restrict__ h2,
                          const float* __restrict__ gamma,
                          const float* __restrict__ beta,
                          float* __restrict__ outp, int relu) {
    int t = blockIdx.x * blockDim.x + threadIdx.x;
    int node = t >> 5, lane = t & 31;
    if (node >= NN) return;
    const float inv = 1.0f / (float)NN;
    float4 s  = ((const float4*)g_sum)[lane];
    float4 s2 = ((const float4*)g_sumsq)[lane];
    float4 gm = ((const float4*)gamma)[lane];
    float4 bt = ((const float4*)beta)[lane];
    float4 v  = ((const float4*)h2)[(size_t)node * 32 + lane];
    float4 o;
    {
        float mean = s.x * inv; float var = s2.x * inv - mean * mean;
        float sc = gm.x * rsqrtf(var + BN_EPS);
        o.x = (v.x - mean) * sc + bt.x;
    }
    {
        float mean = s.y * inv; float var = s2.y * inv - mean * mean;
        float sc = gm.y * rsqrtf(var + BN_EPS);
        o.y = (v.y - mean) * sc + bt.y;
    }
    {
        float mean = s.z * inv; float var = s2.z * inv - mean * mean;
        float sc = gm.z * rsqrtf(var + BN_EPS);
        o.z = (v.z - mean) * sc + bt.z;
    }
    {
        float mean = s.w * inv; float var = s2.w * inv - mean * mean;
        float sc = gm.w * rsqrtf(var + BN_EPS);
        o.w = (v.w - mean) * sc + bt.w;
    }
    if (relu) {
        o.x = fmaxf(o.x, 0.f); o.y = fmaxf(o.y, 0.f);
        o.z = fmaxf(o.z, 0.f); o.w = fmaxf(o.w, 0.f);
    }
    ((float4*)outp)[(size_t)node * 32 + lane] = o;
}

// ---------------- launch --------------------------------------------------------
extern "C" void kernel_launch(void* const* d_in, const int* in_sizes, int n_in,
                              void* d_out, int out_size) {
    const int*   x     = (const int*)d_in[0];
    const int*   ei    = (const int*)d_in[1];
    const int*   ea    = (const int*)d_in[2];
    const float* atom  = (const float*)d_in[3];
    const float* chir  = (const float*)d_in[4];
    const float* hyb   = (const float*)d_in[5];
    const float* e1    = (const float*)d_in[6];
    const float* e2    = (const float*)d_in[7];
    const float* W1    = (const float*)d_in[8];
    const float* b1    = (const float*)d_in[9];
    const float* W2    = (const float*)d_in[10];
    const float* b2    = (const float*)d_in[11];
    const float* gamma = (const float*)d_in[12];
    const float* beta  = (const float*)d_in[13];
    float* out = (float*)d_out;

    float *p_h, *p_agg, *p_mid, *p_h2;
    cudaGetSymbolAddress((void**)&p_h,   g_h);
    cudaGetSymbolAddress((void**)&p_agg, g_agg);
    cudaGetSymbolAddress((void**)&p_mid, g_mid);
    cudaGetSymbolAddress((void**)&p_h2,  g_h2);

    const int TPB = 256;
    const int node_blocks = (NN * 32 + TPB - 1) / TPB;
    const int edge_blocks = (NE * 32 + TPB - 1) / TPB;
    const int mrows = (NN + 127) / 128;

    embed_kernel<<<node_blocks, TPB>>>(x, atom, chir, hyb);

    for (int l = 0; l < 5; ++l) {
        cudaMemsetAsync(p_agg, 0, (size_t)NN * D * sizeof(float));
        scatter_kernel<<<edge_blocks, TPB>>>(ei, ea,
                                             e1 + (size_t)l * 6 * D,
                                             e2 + (size_t)l * 4 * D);
        // Linear1 (d -> 2d) + ReLU
        gemm_kernel<<<dim3(2, mrows), 256>>>(p_agg, W1 + (size_t)l * D * 2 * D,
                                             b1 + (size_t)l * 2 * D, p_mid,
                                             NN, 2 * D, D, 1);
        // Linear2 (2d -> d)
        gemm_kernel<<<dim3(1, mrows), 256>>>(p_mid, W2 + (size_t)l * 2 * D * D,
                                             b2 + (size_t)l * D, p_h2,
                                             NN, D, 2 * D, 0);
        zero_stats_kernel<<<1, 128>>>();
        stats_kernel<<<200, 512>>>(p_h2);
        bn_kernel<<<node_blocks, TPB>>>(p_h2, gamma + (size_t)l * D,
                                        beta + (size_t)l * D,
                                        (l == 4) ? out : p_h, (l < 4) ? 1 : 0);
    }
}

// round 3
// speedup vs baseline: 1.1263x; 1.1263x over previous
#include <cuda_runtime.h>
#include <cuda_bf16.h>
#include <cstdint>
#include <cstddef>

#define NN 50000
#define NE 600000
#define D 128
#define BN_EPS 1e-5f

// ---------------- scratch (device globals; no runtime allocation) -------------
__device__ float g_h[NN * D];        // node features between layers
__device__ float g_agg[NN * D];      // scatter-add destination
__device__ float g_mid[NN * 2 * D];  // hidden after Linear1+ReLU
__device__ float g_h2[NN * D];       // after Linear2 (pre-BN)
__device__ float g_sum[D];
__device__ float g_sumsq[D];

// ---------------- input embedding: h = atom[x0] + chir[x1] + hyb[x2] ----------
__global__ void embed_kernel(const int* __restrict__ x,
                             const float* __restrict__ atom,
                             const float* __restrict__ chir,
                             const float* __restrict__ hyb) {
    int t = blockIdx.x * blockDim.x + threadIdx.x;
    int node = t >> 5, lane = t & 31;
    if (node >= NN) return;
    int x0 = x[node * 3 + 0];
    int x1 = x[node * 3 + 1];
    int x2 = x[node * 3 + 2];
    float4 a = ((const float4*)(atom + (size_t)x0 * D))[lane];
    float4 c = ((const float4*)(chir + (size_t)x1 * D))[lane];
    float4 y = ((const float4*)(hyb  + (size_t)x2 * D))[lane];
    float4 r = make_float4(a.x + c.x + y.x, a.y + c.y + y.y,
                           a.z + c.z + y.z, a.w + c.w + y.w);
    ((float4*)g_h)[(size_t)node * 32 + lane] = r;
}

// ---------------- edge message + scatter-add (one warp per edge) --------------
__global__ void scatter_kernel(const int* __restrict__ ei,
                               const int* __restrict__ ea,
                               const float* __restrict__ e1l,
                               const float* __restrict__ e2l) {
    int t = blockIdx.x * blockDim.x + threadIdx.x;
    int e = t >> 5, lane = t & 31;
    if (e >= NE) return;
    int s  = ei[e];
    int dn = ei[NE + e];
    int a0 = ea[2 * e + 0];
    int a1 = ea[2 * e + 1];
    float4 vh = ((const float4*)g_h)[(size_t)s * 32 + lane];
    float4 v1 = ((const float4*)(e1l + (size_t)a0 * D))[lane];
    float4 v2 = ((const float4*)(e2l + (size_t)a1 * D))[lane];
    float* dst = g_agg + (size_t)dn * D + lane * 4;
    atomicAdd(dst + 0, vh.x + v1.x + v2.x);
    atomicAdd(dst + 1, vh.y + v1.y + v2.y);
    atomicAdd(dst + 2, vh.z + v1.z + v2.z);
    atomicAdd(dst + 3, vh.w + v1.w + v2.w);
}

// ---------------- 3xTF32 tensor-core GEMM: C = act(A@B + bias) ----------------
// BM=BN=128, BK=32, 256 threads (8 warps as 4x2), m16n8k8 mma.sync.
// Each operand split v = hi + lo (both tf32); accumulate hi*hi + lo*hi + hi*lo.
__device__ __forceinline__ uint32_t tf32_rna_u(float x) {
    uint32_t u;
    asm("cvt.rna.tf32.f32 %0, %1;" : "=r"(u) : "f"(x));
    return u;
}

__device__ __forceinline__ void split_tf32(float v, uint32_t& hi, uint32_t& lo) {
    hi = tf32_rna_u(v);
    lo = tf32_rna_u(v - __uint_as_float(hi));
}

#define MMA_TF32(acc, a, b)                                              \
    asm volatile(                                                        \
        "mma.sync.aligned.m16n8k8.row.col.f32.tf32.tf32.f32 "            \
        "{%0,%1,%2,%3}, {%4,%5,%6,%7}, {%8,%9}, {%0,%1,%2,%3};\n"        \
        : "+f"(acc[0]), "+f"(acc[1]), "+f"(acc[2]), "+f"(acc[3])         \
        : "r"(a[0]), "r"(a[1]), "r"(a[2]), "r"(a[3]),                    \
          "r"(b[0]), "r"(b[1]))

__global__ __launch_bounds__(256) void gemm_tf32x3_kernel(
    const float* __restrict__ A, const float* __restrict__ B,
    const float* __restrict__ bias, float* __restrict__ C,
    int M, int N, int K, int relu) {
    __shared__ __align__(16) float As[128][36];   // raw fp32, padded
    __shared__ __align__(16) float Bs[32][132];   // raw fp32, padded

    const int tid  = threadIdx.x;
    const int warp = tid >> 5, lane = tid & 31;
    const int gid  = lane >> 2;      // 0..7
    const int tig  = lane & 3;       // 0..3
    const int wm   = (warp & 3) * 32;   // warp M offset
    const int wn   = (warp >> 2) * 64;  // warp N offset
    const int cCol = blockIdx.x, cRow = blockIdx.y;
    const int m0   = cRow * 128;
    const int n0b  = cCol * 128;

    float acc[2][8][4];
#pragma unroll
    for (int mi = 0; mi < 2; mi++)
#pragma unroll
        for (int ni = 0; ni < 8; ni++)
#pragma unroll
            for (int q = 0; q < 4; q++) acc[mi][ni][q] = 0.f;

    const int ar = tid >> 3, ac = (tid & 7) << 2;   // A stage: 32 rows x 8 f4
    const int br = tid >> 5, bc = (tid & 31) << 2;  // B stage: 8 rows x 32 f4

    for (int k0 = 0; k0 < K; k0 += 32) {
#pragma unroll
        for (int i = 0; i < 4; i++) {
            int r = ar + i * 32;
            float4 v = make_float4(0.f, 0.f, 0.f, 0.f);
            if (m0 + r < M)
                v = *(const float4*)(A + (size_t)(m0 + r) * K + k0 + ac);
            *(float4*)&As[r][ac] = v;
        }
#pragma unroll
        for (int i = 0; i < 4; i++) {
            int r = br + i * 8;
            *(float4*)&Bs[r][bc] =
                *(const float4*)(B + (size_t)(k0 + r) * N + n0b + bc);
        }
        __syncthreads();

#pragma unroll
        for (int ks = 0; ks < 4; ks++) {
            const int kk = ks * 8;
            uint32_t ah[2][4], al[2][4], bh[8][2], bl[8][2];
#pragma unroll
            for (int mi = 0; mi < 2; mi++) {
                int r0 = wm + mi * 16 + gid;
                split_tf32(As[r0][kk + tig],         ah[mi][0], al[mi][0]);
                split_tf32(As[r0 + 8][kk + tig],     ah[mi][1], al[mi][1]);
                split_tf32(As[r0][kk + tig + 4],     ah[mi][2], al[mi][2]);
                split_tf32(As[r0 + 8][kk + tig + 4], ah[mi][3], al[mi][3]);
            }
#pragma unroll
            for (int ni = 0; ni < 8; ni++) {
                int c0 = wn + ni * 8 + gid;
                split_tf32(Bs[kk + tig][c0],     bh[ni][0], bl[ni][0]);
                split_tf32(Bs[kk + tig + 4][c0], bh[ni][1], bl[ni][1]);
            }
#pragma unroll
            for (int mi = 0; mi < 2; mi++)
#pragma unroll
                for (int ni = 0; ni < 8; ni++) {
                    MMA_TF32(acc[mi][ni], al[mi], bh[ni]);  // lo*hi
                    MMA_TF32(acc[mi][ni], ah[mi], bl[ni]);  // hi*lo
                    MMA_TF32(acc[mi][ni], ah[mi], bh[ni]);  // hi*hi
                }
        }
        __syncthreads();
    }

    // epilogue: bias + optional ReLU, float2 stores
#pragma unroll
    for (int mi = 0; mi < 2; mi++) {
        int r0 = m0 + wm + mi * 16 + gid;
#pragma unroll
        for (int ni = 0; ni < 8; ni++) {
            int gc = n0b + wn + ni * 8 + 2 * tig;
            float bv0 = bias[gc], bv1 = bias[gc + 1];
            float v0 = acc[mi][ni][0] + bv0;
            float v1 = acc[mi][ni][1] + bv1;
            float v2 = acc[mi][ni][2] + bv0;
            float v3 = acc[mi][ni][3] + bv1;
            if (relu) {
                v0 = fmaxf(v0, 0.f); v1 = fmaxf(v1, 0.f);
                v2 = fmaxf(v2, 0.f); v3 = fmaxf(v3, 0.f);
            }
            if (r0 < M)
                *(float2*)(C + (size_t)r0 * N + gc) = make_float2(v0, v1);
            if (r0 + 8 < M)
                *(float2*)(C + (size_t)(r0 + 8) * N + gc) = make_float2(v2, v3);
        }
    }
}

// ---------------- BN batch statistics ------------------------------------------
__global__ void zero_stats_kernel() {
    g_sum[threadIdx.x] = 0.f;
    g_sumsq[threadIdx.x] = 0.f;
}

__global__ void stats_kernel(const float* __restrict__ h2) {
    int col = threadIdx.x & 127;
    int rpb = blockDim.x >> 7;
    int r = blockIdx.x * rpb + (threadIdx.x >> 7);
    int stride = gridDim.x * rpb;
    float s = 0.f, s2 = 0.f;
    for (; r < NN; r += stride) {
        float v = h2[(size_t)r * D + col];
        s += v;
        s2 += v * v;
    }
    atomicAdd(&g_sum[col], s);
    atomicAdd(&g_sumsq[col], s2);
}

__global__ void bn_kernel(const float* __restrict__ h2,
                          const float* __restrict__ gamma,
                          const float* __restrict__ beta,
                          float* __restrict__ outp, int relu) {
    int t = blockIdx.x * blockDim.x + threadIdx.x;
    int node = t >> 5, lane = t & 31;
    if (node >= NN) return;
    const float inv = 1.0f / (float)NN;
    float4 s  = ((const float4*)g_sum)[lane];
    float4 s2 = ((const float4*)g_sumsq)[lane];
    float4 gm = ((const float4*)gamma)[lane];
    float4 bt = ((const float4*)beta)[lane];
    float4 v  = ((const float4*)h2)[(size_t)node * 32 + lane];
    float4 o;
    {
        float mean = s.x * inv; float var = s2.x * inv - mean * mean;
        float sc = gm.x * rsqrtf(var + BN_EPS);
        o.x = (v.x - mean) * sc + bt.x;
    }
    {
        float mean = s.y * inv; float var = s2.y * inv - mean * mean;
        float sc = gm.y * rsqrtf(var + BN_EPS);
        o.y = (v.y - mean) * sc + bt.y;
    }
    {
        float mean = s.z * inv; float var = s2.z * inv - mean * mean;
        float sc = gm.z * rsqrtf(var + BN_EPS);
        o.z = (v.z - mean) * sc + bt.z;
    }
    {
        float mean = s.w * inv; float var = s2.w * inv - mean * mean;
        float sc = gm.w * rsqrtf(var + BN_EPS);
        o.w = (v.w - mean) * sc + bt.w;
    }
    if (relu) {
        o.x = fmaxf(o.x, 0.f); o.y = fmaxf(o.y, 0.f);
        o.z = fmaxf(o.z, 0.f); o.w = fmaxf(o.w, 0.f);
    }
    ((float4*)outp)[(size_t)node * 32 + lane] = o;
}

// ---------------- launch --------------------------------------------------------
extern "C" void kernel_launch(void* const* d_in, const int* in_sizes, int n_in,
                              void* d_out, int out_size) {
    const int*   x     = (const int*)d_in[0];
    const int*   ei    = (const int*)d_in[1];
    const int*   ea    = (const int*)d_in[2];
    const float* atom  = (const float*)d_in[3];
    const float* chir  = (const float*)d_in[4];
    const float* hyb   = (const float*)d_in[5];
    const float* e1    = (const float*)d_in[6];
    const float* e2    = (const float*)d_in[7];
    const float* W1    = (const float*)d_in[8];
    const float* b1    = (const float*)d_in[9];
    const float* W2    = (const float*)d_in[10];
    const float* b2    = (const float*)d_in[11];
    const float* gamma = (const float*)d_in[12];
    const float* beta  = (const float*)d_in[13];
    float* out = (float*)d_out;

    float *p_h, *p_agg, *p_mid, *p_h2;
    cudaGetSymbolAddress((void**)&p_h,   g_h);
    cudaGetSymbolAddress((void**)&p_agg, g_agg);
    cudaGetSymbolAddress((void**)&p_mid, g_mid);
    cudaGetSymbolAddress((void**)&p_h2,  g_h2);

    const int TPB = 256;
    const int node_blocks = (NN * 32 + TPB - 1) / TPB;
    const int edge_blocks = (NE * 32 + TPB - 1) / TPB;
    const int mrows = (NN + 127) / 128;

    embed_kernel<<<node_blocks, TPB>>>(x, atom, chir, hyb);

    for (int l = 0; l < 5; ++l) {
        cudaMemsetAsync(p_agg, 0, (size_t)NN * D * sizeof(float));
        scatter_kernel<<<edge_blocks, TPB>>>(ei, ea,
                                             e1 + (size_t)l * 6 * D,
                                             e2 + (size_t)l * 4 * D);
        // Linear1 (d -> 2d) + ReLU
        gemm_tf32x3_kernel<<<dim3(2, mrows), 256>>>(p_agg, W1 + (size_t)l * D * 2 * D,
                                                    b1 + (size_t)l * 2 * D, p_mid,
                                                    NN, 2 * D, D, 1);
        // Linear2 (2d -> d)
        gemm_tf32x3_kernel<<<dim3(1, mrows), 256>>>(p_mid, W2 + (size_t)l * 2 * D * D,
                                                    b2 + (size_t)l * D, p_h2,
                                                    NN, D, 2 * D, 0);
        zero_stats_kernel<<<1, 128>>>();
        stats_kernel<<<200, 512>>>(p_h2);
        bn_kernel<<<node_blocks, TPB>>>(p_h2, gamma + (size_t)l * D,
                                        beta + (size_t)l * D,
                                        (l == 4) ? out : p_h, (l < 4) ? 1 : 0);
    }
}

// round 4
// speedup vs baseline: 1.8994x; 1.6864x over previous
#include <cuda_runtime.h>
#include <cuda_bf16.h>
#include <cstdint>
#include <cstddef>

#define NN 50000
#define NE 600000
#define D 128
#define BN_EPS 1e-5f

// ---------------- scratch (device globals; no runtime allocation) -------------
__device__ float g_h[NN * D];
__device__ float g_agg[NN * D];
__device__ float g_mid[NN * 2 * D];
__device__ float g_h2[NN * D];
__device__ float g_sum[D];
__device__ float g_sumsq[D];
// CSR structures
__device__ int   g_cnt[NN];
__device__ int   g_rowstart[NN + 1];
__device__ int   g_cursor[NN];
__device__ int   g_edges[NE];          // src | (combo << 16)
__device__ float g_eec[24 * D];        // per-layer edge-combo embeddings

// ---------------- input embedding ---------------------------------------------
__global__ void embed_kernel(const int* __restrict__ x,
                             const float* __restrict__ atom,
                             const float* __restrict__ chir,
                             const float* __restrict__ hyb) {
    int t = blockIdx.x * blockDim.x + threadIdx.x;
    int node = t >> 5, lane = t & 31;
    if (node >= NN) return;
    int x0 = x[node * 3 + 0];
    int x1 = x[node * 3 + 1];
    int x2 = x[node * 3 + 2];
    float4 a = ((const float4*)(atom + (size_t)x0 * D))[lane];
    float4 c = ((const float4*)(chir + (size_t)x1 * D))[lane];
    float4 y = ((const float4*)(hyb  + (size_t)x2 * D))[lane];
    ((float4*)g_h)[(size_t)node * 32 + lane] =
        make_float4(a.x + c.x + y.x, a.y + c.y + y.y,
                    a.z + c.z + y.z, a.w + c.w + y.w);
}

// ---------------- CSR build ----------------------------------------------------
__global__ void count_kernel(const int* __restrict__ ei) {
    int e = blockIdx.x * blockDim.x + threadIdx.x;
    if (e >= NE) return;
    atomicAdd(&g_cnt[ei[NE + e]], 1);
}

__global__ void scan_kernel() {
    __shared__ int warpsum[32];
    __shared__ int carry;
    int lane = threadIdx.x & 31, wid = threadIdx.x >> 5;
    if (threadIdx.x == 0) carry = 0;
    __syncthreads();
    for (int base = 0; base < NN; base += 1024) {
        int i = base + threadIdx.x;
        int v = (i < NN) ? g_cnt[i] : 0;
        int xs = v;
#pragma unroll
        for (int off = 1; off < 32; off <<= 1) {
            int t = __shfl_up_sync(0xffffffff, xs, off);
            if (lane >= off) xs += t;
        }
        if (lane == 31) warpsum[wid] = xs;
        __syncthreads();
        if (wid == 0) {
            int w = warpsum[lane];
#pragma unroll
            for (int off = 1; off < 32; off <<= 1) {
                int t = __shfl_up_sync(0xffffffff, w, off);
                if (lane >= off) w += t;
            }
            warpsum[lane] = w;
        }
        __syncthreads();
        int wpre = (wid > 0) ? warpsum[wid - 1] : 0;
        int incl = xs + wpre;
        int excl = incl - v + carry;
        if (i < NN) { g_rowstart[i] = excl; g_cursor[i] = excl; }
        __syncthreads();
        if (threadIdx.x == 1023) carry += incl;
        __syncthreads();
    }
    if (threadIdx.x == 0) g_rowstart[NN] = carry;
}

__global__ void fill_kernel(const int* __restrict__ ei,
                            const int* __restrict__ ea) {
    int e = blockIdx.x * blockDim.x + threadIdx.x;
    if (e >= NE) return;
    int dst = ei[NE + e];
    int pos = atomicAdd(&g_cursor[dst], 1);
    int cb = ea[2 * e] * 4 + ea[2 * e + 1];
    g_edges[pos] = ei[e] | (cb << 16);
}

// ---------------- per-layer edge-combo table: eec[a0*4+a1] = e1[a0]+e2[a1] -----
__global__ void eec_kernel(const float* __restrict__ e1l,
                           const float* __restrict__ e2l) {
    int cb = blockIdx.x;           // 0..23
    int lane = threadIdx.x;        // 0..31
    int a0 = cb >> 2, a1 = cb & 3;
    float4 v1 = ((const float4*)(e1l + (size_t)a0 * D))[lane];
    float4 v2 = ((const float4*)(e2l + (size_t)a1 * D))[lane];
    ((float4*)g_eec)[cb * 32 + lane] =
        make_float4(v1.x + v2.x, v1.y + v2.y, v1.z + v2.z, v1.w + v2.w);
}

// ---------------- gather-aggregate: one warp per dst node ----------------------
__global__ void agg_kernel(const float* __restrict__ h) {
    int t = blockIdx.x * blockDim.x + threadIdx.x;
    int n = t >> 5, lane = t & 31;
    if (n >= NN) return;
    int beg = g_rowstart[n], end = g_rowstart[n + 1];
    float4 acc = make_float4(0.f, 0.f, 0.f, 0.f);
    int i = beg;
    for (; i + 1 < end; i += 2) {
        int p0 = g_edges[i];
        int p1 = g_edges[i + 1];
        float4 a  = ((const float4*)h)[(size_t)(p0 & 0xFFFF) * 32 + lane];
        float4 b  = ((const float4*)h)[(size_t)(p1 & 0xFFFF) * 32 + lane];
        float4 ea0 = ((const float4*)g_eec)[(p0 >> 16) * 32 + lane];
        float4 eb0 = ((const float4*)g_eec)[(p1 >> 16) * 32 + lane];
        acc.x += (a.x + ea0.x) + (b.x + eb0.x);
        acc.y += (a.y + ea0.y) + (b.y + eb0.y);
        acc.z += (a.z + ea0.z) + (b.z + eb0.z);
        acc.w += (a.w + ea0.w) + (b.w + eb0.w);
    }
    if (i < end) {
        int p0 = g_edges[i];
        float4 a  = ((const float4*)h)[(size_t)(p0 & 0xFFFF) * 32 + lane];
        float4 ea0 = ((const float4*)g_eec)[(p0 >> 16) * 32 + lane];
        acc.x += a.x + ea0.x;
        acc.y += a.y + ea0.y;
        acc.z += a.z + ea0.z;
        acc.w += a.w + ea0.w;
    }
    ((float4*)g_agg)[(size_t)n * 32 + lane] = acc;
}

// ---------------- 3xTF32 tensor-core GEMM with staged hi/lo split --------------
__device__ __forceinline__ uint32_t tf32_rna_u(float x) {
    uint32_t u;
    asm("cvt.rna.tf32.f32 %0, %1;" : "=r"(u) : "f"(x));
    return u;
}

#define MMA_TF32(acc, a, b)                                              \
    asm volatile(                                                        \
        "mma.sync.aligned.m16n8k8.row.col.f32.tf32.tf32.f32 "            \
        "{%0,%1,%2,%3}, {%4,%5,%6,%7}, {%8,%9}, {%0,%1,%2,%3};\n"        \
        : "+f"(acc[0]), "+f"(acc[1]), "+f"(acc[2]), "+f"(acc[3])         \
        : "r"(a[0]), "r"(a[1]), "r"(a[2]), "r"(a[3]),                    \
          "r"(b[0]), "r"(b[1]))

// dynamic smem layout (floats): As_hi[128*36] As_lo[128*36] Bs_hi[32*132] Bs_lo[32*132]
#define SM_ASZ (128 * 36)
#define SM_BSZ (32 * 132)
#define SMEM_FLOATS (2 * SM_ASZ + 2 * SM_BSZ)

__global__ __launch_bounds__(256) void gemm_tf32x3_kernel(
    const float* __restrict__ A, const float* __restrict__ B,
    const float* __restrict__ bias, float* __restrict__ C,
    int M, int N, int K, int relu) {
    extern __shared__ float sm[];
    float* As_hi = sm;
    float* As_lo = sm + SM_ASZ;
    float* Bs_hi = sm + 2 * SM_ASZ;
    float* Bs_lo = sm + 2 * SM_ASZ + SM_BSZ;

    const int tid  = threadIdx.x;
    const int warp = tid >> 5, lane = tid & 31;
    const int gid  = lane >> 2;
    const int tig  = lane & 3;
    const int wm   = (warp & 3) * 32;
    const int wn   = (warp >> 2) * 64;
    const int m0   = blockIdx.y * 128;
    const int n0b  = blockIdx.x * 128;

    float acc[2][8][4];
#pragma unroll
    for (int mi = 0; mi < 2; mi++)
#pragma unroll
        for (int ni = 0; ni < 8; ni++)
#pragma unroll
            for (int q = 0; q < 4; q++) acc[mi][ni][q] = 0.f;

    const int ar = tid >> 3, ac = (tid & 7) << 2;
    const int br = tid >> 5, bc = (tid & 31) << 2;

    for (int k0 = 0; k0 < K; k0 += 32) {
#pragma unroll
        for (int i = 0; i < 4; i++) {
            int r = ar + i * 32;
            float4 v = make_float4(0.f, 0.f, 0.f, 0.f);
            if (m0 + r < M)
                v = *(const float4*)(A + (size_t)(m0 + r) * K + k0 + ac);
            uint32_t hx = tf32_rna_u(v.x), hy = tf32_rna_u(v.y),
                     hz = tf32_rna_u(v.z), hw = tf32_rna_u(v.w);
            uint32_t lx = tf32_rna_u(v.x - __uint_as_float(hx));
            uint32_t ly = tf32_rna_u(v.y - __uint_as_float(hy));
            uint32_t lz = tf32_rna_u(v.z - __uint_as_float(hz));
            uint32_t lw = tf32_rna_u(v.w - __uint_as_float(hw));
            *(float4*)&As_hi[r * 36 + ac] =
                make_float4(__uint_as_float(hx), __uint_as_float(hy),
                            __uint_as_float(hz), __uint_as_float(hw));
            *(float4*)&As_lo[r * 36 + ac] =
                make_float4(__uint_as_float(lx), __uint_as_float(ly),
                            __uint_as_float(lz), __uint_as_float(lw));
        }
#pragma unroll
        for (int i = 0; i < 4; i++) {
            int r = br + i * 8;
            float4 v = *(const float4*)(B + (size_t)(k0 + r) * N + n0b + bc);
            uint32_t hx = tf32_rna_u(v.x), hy = tf32_rna_u(v.y),
                     hz = tf32_rna_u(v.z), hw = tf32_rna_u(v.w);
            uint32_t lx = tf32_rna_u(v.x - __uint_as_float(hx));
            uint32_t ly = tf32_rna_u(v.y - __uint_as_float(hy));
            uint32_t lz = tf32_rna_u(v.z - __uint_as_float(hz));
            uint32_t lw = tf32_rna_u(v.w - __uint_as_float(hw));
            *(float4*)&Bs_hi[r * 132 + bc] =
                make_float4(__uint_as_float(hx), __uint_as_float(hy),
                            __uint_as_float(hz), __uint_as_float(hw));
            *(float4*)&Bs_lo[r * 132 + bc] =
                make_float4(__uint_as_float(lx), __uint_as_float(ly),
                            __uint_as_float(lz), __uint_as_float(lw));
        }
        __syncthreads();

#pragma unroll
        for (int ks = 0; ks < 4; ks++) {
            const int kk = ks * 8;
            uint32_t ah[2][4], al[2][4], bh[8][2], bl[8][2];
#pragma unroll
            for (int mi = 0; mi < 2; mi++) {
                int r0 = wm + mi * 16 + gid;
                ah[mi][0] = __float_as_uint(As_hi[r0 * 36 + kk + tig]);
                ah[mi][1] = __float_as_uint(As_hi[(r0 + 8) * 36 + kk + tig]);
                ah[mi][2] = __float_as_uint(As_hi[r0 * 36 + kk + tig + 4]);
                ah[mi][3] = __float_as_uint(As_hi[(r0 + 8) * 36 + kk + tig + 4]);
                al[mi][0] = __float_as_uint(As_lo[r0 * 36 + kk + tig]);
                al[mi][1] = __float_as_uint(As_lo[(r0 + 8) * 36 + kk + tig]);
                al[mi][2] = __float_as_uint(As_lo[r0 * 36 + kk + tig + 4]);
                al[mi][3] = __float_as_uint(As_lo[(r0 + 8) * 36 + kk + tig + 4]);
            }
#pragma unroll
            for (int ni = 0; ni < 8; ni++) {
                int c0 = wn + ni * 8 + gid;
                bh[ni][0] = __float_as_uint(Bs_hi[(kk + tig) * 132 + c0]);
                bh[ni][1] = __float_as_uint(Bs_hi[(kk + tig + 4) * 132 + c0]);
                bl[ni][0] = __float_as_uint(Bs_lo[(kk + tig) * 132 + c0]);
                bl[ni][1] = __float_as_uint(Bs_lo[(kk + tig + 4) * 132 + c0]);
            }
#pragma unroll
            for (int mi = 0; mi < 2; mi++)
#pragma unroll
                for (int ni = 0; ni < 8; ni++) {
                    MMA_TF32(acc[mi][ni], al[mi], bh[ni]);  // lo*hi
                    MMA_TF32(acc[mi][ni], ah[mi], bl[ni]);  // hi*lo
                    MMA_TF32(acc[mi][ni], ah[mi], bh[ni]);  // hi*hi
                }
        }
        __syncthreads();
    }

#pragma unroll
    for (int mi = 0; mi < 2; mi++) {
        int r0 = m0 + wm + mi * 16 + gid;
#pragma unroll
        for (int ni = 0; ni < 8; ni++) {
            int gc = n0b + wn + ni * 8 + 2 * tig;
            float bv0 = bias[gc], bv1 = bias[gc + 1];
            float v0 = acc[mi][ni][0] + bv0;
            float v1 = acc[mi][ni][1] + bv1;
            float v2 = acc[mi][ni][2] + bv0;
            float v3 = acc[mi][ni][3] + bv1;
            if (relu) {
                v0 = fmaxf(v0, 0.f); v1 = fmaxf(v1, 0.f);
                v2 = fmaxf(v2, 0.f); v3 = fmaxf(v3, 0.f);
            }
            if (r0 < M)
                *(float2*)(C + (size_t)r0 * N + gc) = make_float2(v0, v1);
            if (r0 + 8 < M)
                *(float2*)(C + (size_t)(r0 + 8) * N + gc) = make_float2(v2, v3);
        }
    }
}

// ---------------- BN ------------------------------------------------------------
__global__ void zero_stats_kernel() {
    g_sum[threadIdx.x] = 0.f;
    g_sumsq[threadIdx.x] = 0.f;
}

__global__ void stats_kernel(const float* __restrict__ h2) {
    int col = threadIdx.x & 127;
    int rpb = blockDim.x >> 7;
    int r = blockIdx.x * rpb + (threadIdx.x >> 7);
    int stride = gridDim.x * rpb;
    float s = 0.f, s2 = 0.f;
    for (; r < NN; r += stride) {
        float v = h2[(size_t)r * D + col];
        s += v;
        s2 += v * v;
    }
    atomicAdd(&g_sum[col], s);
    atomicAdd(&g_sumsq[col], s2);
}

__global__ void bn_kernel(const float* __restrict__ h2,
                          const float* __restrict__ gamma,
                          const float* __restrict__ beta,
                          float* __restrict__ outp, int relu) {
    int t = blockIdx.x * blockDim.x + threadIdx.x;
    int node = t >> 5, lane = t & 31;
    if (node >= NN) return;
    const float inv = 1.0f / (float)NN;
    float4 s  = ((const float4*)g_sum)[lane];
    float4 s2 = ((const float4*)g_sumsq)[lane];
    float4 gm = ((const float4*)gamma)[lane];
    float4 bt = ((const float4*)beta)[lane];
    float4 v  = ((const float4*)h2)[(size_t)node * 32 + lane];
    float4 o;
    { float mean = s.x*inv; float var = s2.x*inv - mean*mean;
      o.x = (v.x-mean)*(gm.x*rsqrtf(var+BN_EPS)) + bt.x; }
    { float mean = s.y*inv; float var = s2.y*inv - mean*mean;
      o.y = (v.y-mean)*(gm.y*rsqrtf(var+BN_EPS)) + bt.y; }
    { float mean = s.z*inv; float var = s2.z*inv - mean*mean;
      o.z = (v.z-mean)*(gm.z*rsqrtf(var+BN_EPS)) + bt.z; }
    { float mean = s.w*inv; float var = s2.w*inv - mean*mean;
      o.w = (v.w-mean)*(gm.w*rsqrtf(var+BN_EPS)) + bt.w; }
    if (relu) {
        o.x = fmaxf(o.x, 0.f); o.y = fmaxf(o.y, 0.f);
        o.z = fmaxf(o.z, 0.f); o.w = fmaxf(o.w, 0.f);
    }
    ((float4*)outp)[(size_t)node * 32 + lane] = o;
}

// ---------------- launch --------------------------------------------------------
extern "C" void kernel_launch(void* const* d_in, const int* in_sizes, int n_in,
                              void* d_out, int out_size) {
    const int*   x     = (const int*)d_in[0];
    const int*   ei    = (const int*)d_in[1];
    const int*   ea    = (const int*)d_in[2];
    const float* atom  = (const float*)d_in[3];
    const float* chir  = (const float*)d_in[4];
    const float* hyb   = (const float*)d_in[5];
    const float* e1    = (const float*)d_in[6];
    const float* e2    = (const float*)d_in[7];
    const float* W1    = (const float*)d_in[8];
    const float* b1    = (const float*)d_in[9];
    const float* W2    = (const float*)d_in[10];
    const float* b2    = (const float*)d_in[11];
    const float* gamma = (const float*)d_in[12];
    const float* beta  = (const float*)d_in[13];
    float* out = (float*)d_out;

    float *p_h, *p_agg, *p_mid, *p_h2;
    int* p_cnt;
    cudaGetSymbolAddress((void**)&p_h,   g_h);
    cudaGetSymbolAddress((void**)&p_agg, g_agg);
    cudaGetSymbolAddress((void**)&p_mid, g_mid);
    cudaGetSymbolAddress((void**)&p_h2,  g_h2);
    cudaGetSymbolAddress((void**)&p_cnt, g_cnt);

    const size_t smbytes = SMEM_FLOATS * sizeof(float);  // 70656
    cudaFuncSetAttribute(gemm_tf32x3_kernel,
                         cudaFuncAttributeMaxDynamicSharedMemorySize,
                         (int)smbytes);

    const int TPB = 256;
    const int node_blocks = (NN * 32 + TPB - 1) / TPB;
    const int edge_blocks = (NE + TPB - 1) / TPB;
    const int mrows = (NN + 127) / 128;

    // CSR build (graph structure is layer-invariant)
    cudaMemsetAsync(p_cnt, 0, NN * sizeof(int));
    count_kernel<<<edge_blocks, TPB>>>(ei);
    scan_kernel<<<1, 1024>>>();
    fill_kernel<<<edge_blocks, TPB>>>(ei, ea);

    embed_kernel<<<node_blocks, TPB>>>(x, atom, chir, hyb);

    for (int l = 0; l < 5; ++l) {
        eec_kernel<<<24, 32>>>(e1 + (size_t)l * 6 * D, e2 + (size_t)l * 4 * D);
        agg_kernel<<<node_blocks, TPB>>>(p_h);
        gemm_tf32x3_kernel<<<dim3(2, mrows), 256, smbytes>>>(
            p_agg, W1 + (size_t)l * D * 2 * D, b1 + (size_t)l * 2 * D, p_mid,
            NN, 2 * D, D, 1);
        gemm_tf32x3_kernel<<<dim3(1, mrows), 256, smbytes>>>(
            p_mid, W2 + (size_t)l * 2 * D * D, b2 + (size_t)l * D, p_h2,
            NN, D, 2 * D, 0);
        zero_stats_kernel<<<1, 128>>>();
        stats_kernel<<<200, 512>>>(p_h2);
        bn_kernel<<<node_blocks, TPB>>>(p_h2, gamma + (size_t)l * D,
                                        beta + (size_t)l * D,
                                        (l == 4) ? out : p_h, (l < 4) ? 1 : 0);
    }
}